// round 16
// baseline (speedup 1.0000x reference)
#include <cuda_runtime.h>
#include <cuda_fp16.h>
#include <cstdint>

#define NMAX    100000
#define IN_DIM  512
#define HID     16

typedef unsigned long long ull;

// Scratch (allocation-free per harness rules): __device__ globals.
__device__ __half g_xw16[(size_t)NMAX * HID];  // x @ W1 (fp16)    [N,16]
__device__ float  g_h [(size_t)NMAX * HID];    // spmm accumulator [N,16]
__device__ float  g_h2[(size_t)NMAX];          // relu(h+b1) @ W2  [N]
__device__ float2 g_bfrag[64 * 2 * 32];        // tf32 B fragments

// ---------------------------------------------------------------------------
// K0a (side stream): zero g_h + init out = b2   (hidden under gemm)
// ---------------------------------------------------------------------------
__global__ void k_zero_out(const float* __restrict__ b2,
                           float* __restrict__ out, int n4, int n) {
    int i = blockIdx.x * blockDim.x + threadIdx.x;
    if (i < n4) ((float4*)g_h)[i] = make_float4(0.f, 0.f, 0.f, 0.f);
    if (i < n)  out[i] = __ldg(b2);
}

// ---------------------------------------------------------------------------
// K0b (main stream): build tf32 B fragments (gemm's only prerequisite)
// ---------------------------------------------------------------------------
__global__ void k_bfrag(const float* __restrict__ W1) {
    int i = blockIdx.x * blockDim.x + threadIdx.x;
    if (i >= 64 * 2 * 32) return;
    int lane  = i & 31;
    int nt    = (i >> 5) & 1;
    int kstep = i >> 6;
    int grp = lane >> 2, tig = lane & 3;
    int k0 = kstep * 8 + tig;
    int n0 = nt * 8 + grp;
    unsigned u0, u1;
    float b0 = __ldg(W1 + k0 * HID + n0);
    float b1 = __ldg(W1 + (k0 + 4) * HID + n0);
    asm("cvt.rna.tf32.f32 %0, %1;" : "=r"(u0) : "f"(b0));
    asm("cvt.rna.tf32.f32 %0, %1;" : "=r"(u1) : "f"(b1));
    g_bfrag[i] = make_float2(__uint_as_float(u0), __uint_as_float(u1));
}

// ---------------------------------------------------------------------------
// K1: g_xw16 = fp16(x @ W1) via tf32 mma.sync (m16n8k8).
//   296 blocks x 12 warps, one 32-row chunk per warp, B frags from L2,
//   warp-private 3-stage cp.async pipeline (lookahead 2), no block barriers.
// ---------------------------------------------------------------------------
#define KT3     16
#define RPW3    32
#define PADW3   20
#define TILEF3  (RPW3 * PADW3)
#define TPC3    (IN_DIM / KT3)
#define GW3     12
#define STG3    3
#define GSM_B   (GW3 * STG3 * TILEF3 * 4)   // 92160 B

#define MMA_TF32(C, A, B0, B1)                                                \
    asm("mma.sync.aligned.m16n8k8.row.col.f32.tf32.tf32.f32 "                 \
        "{%0,%1,%2,%3}, {%4,%5,%6,%7}, {%8,%9}, {%0,%1,%2,%3};"               \
        : "+f"((C)[0]), "+f"((C)[1]), "+f"((C)[2]), "+f"((C)[3])              \
        : "r"((A)[0]), "r"((A)[1]), "r"((A)[2]), "r"((A)[3]),                 \
          "r"(B0), "r"(B1))

#define GLOAD3(J)                                                             \
    {                                                                         \
        int j_ = (J);                                                         \
        float* dst0 = sB + (j_ % STG3) * TILEF3;                              \
        _Pragma("unroll")                                                     \
        for (int i_ = 0; i_ < 4; ++i_) {                                      \
            int flat = i_ * 32 + lane;                                        \
            int r_ = flat >> 2, q_ = flat & 3;                                \
            unsigned d_ = (unsigned)__cvta_generic_to_shared(                 \
                dst0 + r_ * PADW3 + q_ * 4);                                  \
            long row_ = (long)wg * RPW3 + r_;                                 \
            int ok_ = (row_ < n);                                             \
            const float* s_ = x + (ok_ ? (row_ * IN_DIM                       \
                                          + j_ * KT3 + q_ * 4) : 0);          \
            int sz_ = ok_ ? 16 : 0;                                           \
            asm volatile("cp.async.cg.shared.global [%0], [%1], 16, %2;"      \
                         :: "r"(d_), "l"(s_), "r"(sz_));                      \
        }                                                                     \
        asm volatile("cp.async.commit_group;");                              \
    }

__global__ void __launch_bounds__(384) k_gemm1(
        const float* __restrict__ x, int n) {
    extern __shared__ float sm[];

    int t    = threadIdx.x;
    int w    = t >> 5;
    int lane = t & 31;
    int grp  = lane >> 2;
    int tig  = lane & 3;
    float* sB = sm + w * (STG3 * TILEF3);
    int wg    = blockIdx.x * GW3 + w;

    int nchunks = (n + RPW3 - 1) / RPW3;
    if (wg >= nchunks) return;

    GLOAD3(0);
    GLOAD3(1);

    float c[2][2][4];
#pragma unroll
    for (int mt = 0; mt < 2; ++mt)
#pragma unroll
        for (int nt = 0; nt < 2; ++nt)
#pragma unroll
            for (int q = 0; q < 4; ++q) c[mt][nt][q] = 0.f;

#pragma unroll 1
    for (int j = 0; j < TPC3; ++j) {
        float2 bf[2][2];
#pragma unroll
        for (int kk = 0; kk < 2; ++kk)
#pragma unroll
            for (int nt = 0; nt < 2; ++nt)
                bf[kk][nt] = __ldg(g_bfrag + ((j * 2 + kk) * 2 + nt) * 32 + lane);

        if (j + 2 < TPC3) {
            GLOAD3(j + 2);
            asm volatile("cp.async.wait_group 2;");
        } else {
            int r = TPC3 - 1 - j;
            if (r == 1) asm volatile("cp.async.wait_group 1;");
            else        asm volatile("cp.async.wait_group 0;");
        }
        __syncwarp();

        const float* sX = sB + (j % STG3) * TILEF3;
#pragma unroll
        for (int kk = 0; kk < 2; ++kk) {
            unsigned a[2][4];
#pragma unroll
            for (int mt = 0; mt < 2; ++mt) {
                int r0 = mt * 16 + grp;
                const float* p0 = sX + r0 * PADW3 + kk * 8 + tig;
                const float* p1 = p0 + 8 * PADW3;
                a[mt][0] = __float_as_uint(p0[0]);
                a[mt][1] = __float_as_uint(p1[0]);
                a[mt][2] = __float_as_uint(p0[4]);
                a[mt][3] = __float_as_uint(p1[4]);
            }
#pragma unroll
            for (int nt = 0; nt < 2; ++nt) {
                unsigned b0 = __float_as_uint(bf[kk][nt].x);
                unsigned b1 = __float_as_uint(bf[kk][nt].y);
                MMA_TF32(c[0][nt], a[0], b0, b1);
                MMA_TF32(c[1][nt], a[1], b0, b1);
            }
        }
    }

    long rowb = (long)wg * RPW3;
#pragma unroll
    for (int mt = 0; mt < 2; ++mt) {
#pragma unroll
        for (int nt = 0; nt < 2; ++nt) {
            long r0 = rowb + mt * 16 + grp;
            int  cb = nt * 8 + 2 * tig;
            __half2 h0 = __floats2half2_rn(c[mt][nt][0], c[mt][nt][1]);
            __half2 h1 = __floats2half2_rn(c[mt][nt][2], c[mt][nt][3]);
            if (r0 < n)
                *(__half2*)(g_xw16 + r0 * HID + cb) = h0;
            if (r0 + 8 < n)
                *(__half2*)(g_xw16 + (r0 + 8) * HID + cb) = h1;
        }
    }
}

// ---------------------------------------------------------------------------
// K2: g_h[dst] += w * fp32(g_xw16[src])
//   4 consecutive edges per thread-quad: int4/float4 metadata, uint2 fp16
//   gather (1 wf/edge), red.v4 (1 wf/edge).
// ---------------------------------------------------------------------------
__global__ void k_spmm1(const int*   __restrict__ src,
                        const int*   __restrict__ dst,
                        const float* __restrict__ w, int E) {
    int t = blockIdx.x * blockDim.x + threadIdx.x;
    int i = t >> 2;
    int base = i << 2;
    if (base >= E) return;
    int part = t & 3;

    int4   s4, d4;
    float4 w4;
    if (base + 4 <= E) {
        s4 = __ldg((const int4*)  (src + base));
        d4 = __ldg((const int4*)  (dst + base));
        w4 = __ldg((const float4*)(w   + base));
    } else {
        int   sv[4] = {0, 0, 0, 0}, dv[4] = {0, 0, 0, 0};
        float wv[4] = {0.f, 0.f, 0.f, 0.f};
        for (int j = 0; j < 4 && base + j < E; ++j) {
            sv[j] = __ldg(src + base + j);
            dv[j] = __ldg(dst + base + j);
            wv[j] = __ldg(w   + base + j);
        }
        s4 = make_int4(sv[0], sv[1], sv[2], sv[3]);
        d4 = make_int4(dv[0], dv[1], dv[2], dv[3]);
        w4 = make_float4(wv[0], wv[1], wv[2], wv[3]);
    }

    int   s[4] = {s4.x, s4.y, s4.z, s4.w};
    int   d[4] = {d4.x, d4.y, d4.z, d4.w};
    float ww[4] = {w4.x, w4.y, w4.z, w4.w};

    uint2 v[4];
#pragma unroll
    for (int j = 0; j < 4; ++j)
        v[j] = __ldg(((const uint2*)g_xw16) + (((size_t)s[j]) << 2) + part);

#pragma unroll
    for (int j = 0; j < 4; ++j) {
        if (base + j >= E) break;
        float2 f0 = __half22float2(*reinterpret_cast<__half2*>(&v[j].x));
        float2 f1 = __half22float2(*reinterpret_cast<__half2*>(&v[j].y));
        float we = ww[j];
        float* a = g_h + (((size_t)d[j]) << 4) + (part << 2);
        asm volatile("red.global.add.v4.f32 [%0], {%1, %2, %3, %4};"
                     :: "l"(a), "f"(f0.x * we), "f"(f0.y * we),
                        "f"(f1.x * we), "f"(f1.y * we) : "memory");
    }
}

// ---------------------------------------------------------------------------
// K3: g_h2 = relu(g_h + b1) @ W2   (2 threads/row for MLP, shfl reduce)
// ---------------------------------------------------------------------------
__global__ void k_layer2a(const float* __restrict__ b1,
                          const float* __restrict__ W2, int n) {
    int t = blockIdx.x * blockDim.x + threadIdx.x;
    int i = t >> 1;
    if (i >= n) return;
    int part = t & 1;

    float acc = 0.f;
#pragma unroll
    for (int p = 0; p < 2; ++p) {
        int q = part * 2 + p;
        float4 hv = ((const float4*)g_h)[(size_t)i * 4 + q];
        float4 bv = __ldg(((const float4*)b1) + q);
        float4 wv = __ldg(((const float4*)W2) + q);
        acc += fmaxf(hv.x + bv.x, 0.f) * wv.x
             + fmaxf(hv.y + bv.y, 0.f) * wv.y
             + fmaxf(hv.z + bv.z, 0.f) * wv.z
             + fmaxf(hv.w + bv.w, 0.f) * wv.w;
    }
    acc += __shfl_down_sync(0xffffffffu, acc, 1);
    if (part == 0) g_h2[i] = acc;
}

// ---------------------------------------------------------------------------
// K4: out[dst] += w * g_h2[src]
//   1 thread per 8 consecutive edges: 2x int4/float4 metadata, 8 independent
//   gathers issued before 8 scalar REDs (deep MLP).
// ---------------------------------------------------------------------------
__global__ void k_spmm2(const int*   __restrict__ src,
                        const int*   __restrict__ dst,
                        const float* __restrict__ w,
                        float* __restrict__ out, int E) {
    int i = blockIdx.x * blockDim.x + threadIdx.x;
    int base = i << 3;
    if (base >= E) return;

    int   s[8], d[8];
    float ww[8];
    if (base + 8 <= E) {
        int4   sa = __ldg((const int4*)(src + base));
        int4   sb = __ldg((const int4*)(src + base + 4));
        int4   da = __ldg((const int4*)(dst + base));
        int4   db = __ldg((const int4*)(dst + base + 4));
        float4 wa = __ldg((const float4*)(w + base));
        float4 wb = __ldg((const float4*)(w + base + 4));
        s[0] = sa.x; s[1] = sa.y; s[2] = sa.z; s[3] = sa.w;
        s[4] = sb.x; s[5] = sb.y; s[6] = sb.z; s[7] = sb.w;
        d[0] = da.x; d[1] = da.y; d[2] = da.z; d[3] = da.w;
        d[4] = db.x; d[5] = db.y; d[6] = db.z; d[7] = db.w;
        ww[0] = wa.x; ww[1] = wa.y; ww[2] = wa.z; ww[3] = wa.w;
        ww[4] = wb.x; ww[5] = wb.y; ww[6] = wb.z; ww[7] = wb.w;
    } else {
#pragma unroll
        for (int j = 0; j < 8; ++j) { s[j] = 0; d[j] = 0; ww[j] = 0.f; }
        for (int j = 0; j < 8 && base + j < E; ++j) {
            s[j]  = __ldg(src + base + j);
            d[j]  = __ldg(dst + base + j);
            ww[j] = __ldg(w   + base + j);
        }
    }

    float h[8];
#pragma unroll
    for (int j = 0; j < 8; ++j) h[j] = __ldg(g_h2 + s[j]);

#pragma unroll
    for (int j = 0; j < 8; ++j) {
        if (base + j >= E) break;
        atomicAdd(out + d[j], ww[j] * h[j]);
    }
}

// ---------------------------------------------------------------------------
extern "C" void kernel_launch(void* const* d_in, const int* in_sizes, int n_in,
                              void* d_out, int out_size) {
    const float* x   = (const float*)d_in[0];
    const int*   src = (const int*)  d_in[1];
    const int*   dst = (const int*)  d_in[2];
    const float* w   = (const float*)d_in[3];
    const float* W1  = (const float*)d_in[4];
    const float* b1  = (const float*)d_in[5];
    const float* W2  = (const float*)d_in[6];
    const float* b2  = (const float*)d_in[7];
    float* out = (float*)d_out;

    int N = in_sizes[0] / IN_DIM;
    int E = in_sizes[1];

    const int T = 256;

    // lazy one-time resources (created on the uncaptured correctness call)
    static cudaStream_t s2 = nullptr;
    static cudaEvent_t  ev0 = nullptr, ev1 = nullptr;
    if (!s2) {
        cudaStreamCreateWithFlags(&s2, cudaStreamNonBlocking);
        cudaEventCreateWithFlags(&ev0, cudaEventDisableTiming);
        cudaEventCreateWithFlags(&ev1, cudaEventDisableTiming);
        cudaFuncSetAttribute(k_gemm1,
            cudaFuncAttributeMaxDynamicSharedMemorySize, GSM_B);
    }

    // fork: side stream zeroes g_h and inits out while gemm runs on main
    int n4 = N * HID / 4;
    cudaEventRecord(ev0, 0);
    cudaStreamWaitEvent(s2, ev0, 0);
    k_zero_out<<<(n4 + T - 1) / T, T, 0, s2>>>(b2, out, n4, N);
    cudaEventRecord(ev1, s2);

    // main: bfrag -> gemm
    k_bfrag<<<(64 * 2 * 32 + T - 1) / T, T>>>(W1);
    const int GB = 296;
    k_gemm1<<<GB, 384, GSM_B>>>(x, N);

    // join: spmm1 needs both gemm (main) and zero (side)
    cudaStreamWaitEvent(0, ev1, 0);

    int ngroups = (E + 3) >> 2;
    long long t1 = (long long)ngroups * 4;
    k_spmm1<<<(unsigned)((t1 + 511) / 512), 512>>>(src, dst, w, E);

    // per-node relu-dot precompute (2 threads/row)
    long long t2 = (long long)N * 2;
    k_layer2a<<<(unsigned)((t2 + 511) / 512), 512>>>(b1, W2, N);

    // spmm2 (8 edges/thread)
    int ng8 = (E + 7) >> 3;
    k_spmm2<<<(ng8 + 255) / 256, 256>>>(src, dst, w, out, E);
}

// round 17
// speedup vs baseline: 1.0607x; 1.0607x over previous
#include <cuda_runtime.h>
#include <cuda_fp16.h>
#include <cstdint>

#define NMAX    100000
#define IN_DIM  512
#define HID     16

typedef unsigned long long ull;

// Scratch (allocation-free per harness rules): __device__ globals.
__device__ __half g_xw16[(size_t)NMAX * HID];  // x @ W1 (fp16)    [N,16]
__device__ float  g_h [(size_t)NMAX * HID];    // spmm accumulator [N,16]
__device__ float  g_h2[(size_t)NMAX];          // relu(h+b1) @ W2  [N]
__device__ float2 g_bfrag[64 * 2 * 32];        // tf32 B fragments

// ---------------------------------------------------------------------------
// K0 (prep): zero g_h + build tf32 B fragments + init out = b2
// ---------------------------------------------------------------------------
__global__ void k_prep(const float* __restrict__ W1,
                       const float* __restrict__ b2,
                       float* __restrict__ out, int n4, int n) {
    int i = blockIdx.x * blockDim.x + threadIdx.x;
    if (i < n4) ((float4*)g_h)[i] = make_float4(0.f, 0.f, 0.f, 0.f);
    if (i < n)  out[i] = __ldg(b2);
    if (i < 64 * 2 * 32) {
        int lane  = i & 31;
        int nt    = (i >> 5) & 1;
        int kstep = i >> 6;
        int grp = lane >> 2, tig = lane & 3;
        int k0 = kstep * 8 + tig;
        int n0 = nt * 8 + grp;
        unsigned u0, u1;
        float b0 = __ldg(W1 + k0 * HID + n0);
        float b1 = __ldg(W1 + (k0 + 4) * HID + n0);
        asm("cvt.rna.tf32.f32 %0, %1;" : "=r"(u0) : "f"(b0));
        asm("cvt.rna.tf32.f32 %0, %1;" : "=r"(u1) : "f"(b1));
        g_bfrag[i] = make_float2(__uint_as_float(u0), __uint_as_float(u1));
    }
}

// ---------------------------------------------------------------------------
// K1: g_xw16 = fp16(x @ W1) via tf32 mma.sync (m16n8k8).
//   296 blocks x 12 warps, one 32-row chunk per warp, B frags from L2,
//   warp-private 3-stage cp.async pipeline (lookahead 2), no block barriers.
// ---------------------------------------------------------------------------
#define KT3     16
#define RPW3    32
#define PADW3   20
#define TILEF3  (RPW3 * PADW3)
#define TPC3    (IN_DIM / KT3)
#define GW3     12
#define STG3    3
#define GSM_B   (GW3 * STG3 * TILEF3 * 4)   // 92160 B

#define MMA_TF32(C, A, B0, B1)                                                \
    asm("mma.sync.aligned.m16n8k8.row.col.f32.tf32.tf32.f32 "                 \
        "{%0,%1,%2,%3}, {%4,%5,%6,%7}, {%8,%9}, {%0,%1,%2,%3};"               \
        : "+f"((C)[0]), "+f"((C)[1]), "+f"((C)[2]), "+f"((C)[3])              \
        : "r"((A)[0]), "r"((A)[1]), "r"((A)[2]), "r"((A)[3]),                 \
          "r"(B0), "r"(B1))

#define GLOAD3(J)                                                             \
    {                                                                         \
        int j_ = (J);                                                         \
        float* dst0 = sB + (j_ % STG3) * TILEF3;                              \
        _Pragma("unroll")                                                     \
        for (int i_ = 0; i_ < 4; ++i_) {                                      \
            int flat = i_ * 32 + lane;                                        \
            int r_ = flat >> 2, q_ = flat & 3;                                \
            unsigned d_ = (unsigned)__cvta_generic_to_shared(                 \
                dst0 + r_ * PADW3 + q_ * 4);                                  \
            long row_ = (long)wg * RPW3 + r_;                                 \
            int ok_ = (row_ < n);                                             \
            const float* s_ = x + (ok_ ? (row_ * IN_DIM                       \
                                          + j_ * KT3 + q_ * 4) : 0);          \
            int sz_ = ok_ ? 16 : 0;                                           \
            asm volatile("cp.async.cg.shared.global [%0], [%1], 16, %2;"      \
                         :: "r"(d_), "l"(s_), "r"(sz_));                      \
        }                                                                     \
        asm volatile("cp.async.commit_group;");                              \
    }

__global__ void __launch_bounds__(384) k_gemm1(
        const float* __restrict__ x, int n) {
    extern __shared__ float sm[];

    int t    = threadIdx.x;
    int w    = t >> 5;
    int lane = t & 31;
    int grp  = lane >> 2;
    int tig  = lane & 3;
    float* sB = sm + w * (STG3 * TILEF3);
    int wg    = blockIdx.x * GW3 + w;

    int nchunks = (n + RPW3 - 1) / RPW3;
    if (wg >= nchunks) return;

    GLOAD3(0);
    GLOAD3(1);

    float c[2][2][4];
#pragma unroll
    for (int mt = 0; mt < 2; ++mt)
#pragma unroll
        for (int nt = 0; nt < 2; ++nt)
#pragma unroll
            for (int q = 0; q < 4; ++q) c[mt][nt][q] = 0.f;

#pragma unroll 1
    for (int j = 0; j < TPC3; ++j) {
        float2 bf[2][2];
#pragma unroll
        for (int kk = 0; kk < 2; ++kk)
#pragma unroll
            for (int nt = 0; nt < 2; ++nt)
                bf[kk][nt] = __ldg(g_bfrag + ((j * 2 + kk) * 2 + nt) * 32 + lane);

        if (j + 2 < TPC3) {
            GLOAD3(j + 2);
            asm volatile("cp.async.wait_group 2;");
        } else {
            int r = TPC3 - 1 - j;
            if (r == 1) asm volatile("cp.async.wait_group 1;");
            else        asm volatile("cp.async.wait_group 0;");
        }
        __syncwarp();

        const float* sX = sB + (j % STG3) * TILEF3;
#pragma unroll
        for (int kk = 0; kk < 2; ++kk) {
            unsigned a[2][4];
#pragma unroll
            for (int mt = 0; mt < 2; ++mt) {
                int r0 = mt * 16 + grp;
                const float* p0 = sX + r0 * PADW3 + kk * 8 + tig;
                const float* p1 = p0 + 8 * PADW3;
                a[mt][0] = __float_as_uint(p0[0]);
                a[mt][1] = __float_as_uint(p1[0]);
                a[mt][2] = __float_as_uint(p0[4]);
                a[mt][3] = __float_as_uint(p1[4]);
            }
#pragma unroll
            for (int nt = 0; nt < 2; ++nt) {
                unsigned b0 = __float_as_uint(bf[kk][nt].x);
                unsigned b1 = __float_as_uint(bf[kk][nt].y);
                MMA_TF32(c[0][nt], a[0], b0, b1);
                MMA_TF32(c[1][nt], a[1], b0, b1);
            }
        }
    }

    long rowb = (long)wg * RPW3;
#pragma unroll
    for (int mt = 0; mt < 2; ++mt) {
#pragma unroll
        for (int nt = 0; nt < 2; ++nt) {
            long r0 = rowb + mt * 16 + grp;
            int  cb = nt * 8 + 2 * tig;
            __half2 h0 = __floats2half2_rn(c[mt][nt][0], c[mt][nt][1]);
            __half2 h1 = __floats2half2_rn(c[mt][nt][2], c[mt][nt][3]);
            if (r0 < n)
                *(__half2*)(g_xw16 + r0 * HID + cb) = h0;
            if (r0 + 8 < n)
                *(__half2*)(g_xw16 + (r0 + 8) * HID + cb) = h1;
        }
    }
}

// ---------------------------------------------------------------------------
// K2: g_h[dst] += w * fp32(g_xw16[src])
//   4 consecutive edges per thread-quad: int4/float4 metadata, uint2 fp16
//   gather (1 wf/edge), red.v4 (1 wf/edge).
// ---------------------------------------------------------------------------
__global__ void k_spmm1(const int*   __restrict__ src,
                        const int*   __restrict__ dst,
                        const float* __restrict__ w, int E) {
    int t = blockIdx.x * blockDim.x + threadIdx.x;
    int i = t >> 2;
    int base = i << 2;
    if (base >= E) return;
    int part = t & 3;

    int4   s4, d4;
    float4 w4;
    if (base + 4 <= E) {
        s4 = __ldg((const int4*)  (src + base));
        d4 = __ldg((const int4*)  (dst + base));
        w4 = __ldg((const float4*)(w   + base));
    } else {
        int   sv[4] = {0, 0, 0, 0}, dv[4] = {0, 0, 0, 0};
        float wv[4] = {0.f, 0.f, 0.f, 0.f};
        for (int j = 0; j < 4 && base + j < E; ++j) {
            sv[j] = __ldg(src + base + j);
            dv[j] = __ldg(dst + base + j);
            wv[j] = __ldg(w   + base + j);
        }
        s4 = make_int4(sv[0], sv[1], sv[2], sv[3]);
        d4 = make_int4(dv[0], dv[1], dv[2], dv[3]);
        w4 = make_float4(wv[0], wv[1], wv[2], wv[3]);
    }

    int   s[4] = {s4.x, s4.y, s4.z, s4.w};
    int   d[4] = {d4.x, d4.y, d4.z, d4.w};
    float ww[4] = {w4.x, w4.y, w4.z, w4.w};

    uint2 v[4];
#pragma unroll
    for (int j = 0; j < 4; ++j)
        v[j] = __ldg(((const uint2*)g_xw16) + (((size_t)s[j]) << 2) + part);

#pragma unroll
    for (int j = 0; j < 4; ++j) {
        if (base + j >= E) break;
        float2 f0 = __half22float2(*reinterpret_cast<__half2*>(&v[j].x));
        float2 f1 = __half22float2(*reinterpret_cast<__half2*>(&v[j].y));
        float we = ww[j];
        float* a = g_h + (((size_t)d[j]) << 4) + (part << 2);
        asm volatile("red.global.add.v4.f32 [%0], {%1, %2, %3, %4};"
                     :: "l"(a), "f"(f0.x * we), "f"(f0.y * we),
                        "f"(f1.x * we), "f"(f1.y * we) : "memory");
    }
}

// ---------------------------------------------------------------------------
// K3: g_h2 = relu(g_h + b1) @ W2   (2 threads/row: halved load chain, shfl)
// ---------------------------------------------------------------------------
__global__ void k_layer2a(const float* __restrict__ b1,
                          const float* __restrict__ W2, int n) {
    int t = blockIdx.x * blockDim.x + threadIdx.x;
    int i = t >> 1;
    if (i >= n) return;
    int part = t & 1;

    float acc = 0.f;
#pragma unroll
    for (int p = 0; p < 2; ++p) {
        int q = part * 2 + p;
        float4 hv = ((const float4*)g_h)[(size_t)i * 4 + q];
        float4 bv = __ldg(((const float4*)b1) + q);
        float4 wv = __ldg(((const float4*)W2) + q);
        acc += fmaxf(hv.x + bv.x, 0.f) * wv.x
             + fmaxf(hv.y + bv.y, 0.f) * wv.y
             + fmaxf(hv.z + bv.z, 0.f) * wv.z
             + fmaxf(hv.w + bv.w, 0.f) * wv.w;
    }
    acc += __shfl_down_sync(0xffffffffu, acc, 1);
    if (part == 0) g_h2[i] = acc;
}

// ---------------------------------------------------------------------------
// K4: out[dst] += w * g_h2[src]
//   1 thread per 4 consecutive edges: int4/float4 metadata, scalar gathers,
//   scalar REDs.
// ---------------------------------------------------------------------------
__global__ void k_spmm2(const int*   __restrict__ src,
                        const int*   __restrict__ dst,
                        const float* __restrict__ w,
                        float* __restrict__ out, int E) {
    int i = blockIdx.x * blockDim.x + threadIdx.x;
    int base = i << 2;
    if (base >= E) return;

    int4   s4, d4;
    float4 w4;
    if (base + 4 <= E) {
        s4 = __ldg((const int4*)  (src + base));
        d4 = __ldg((const int4*)  (dst + base));
        w4 = __ldg((const float4*)(w   + base));
    } else {
        int   sv[4] = {0, 0, 0, 0}, dv[4] = {0, 0, 0, 0};
        float wv[4] = {0.f, 0.f, 0.f, 0.f};
        for (int j = 0; j < 4 && base + j < E; ++j) {
            sv[j] = __ldg(src + base + j);
            dv[j] = __ldg(dst + base + j);
            wv[j] = __ldg(w   + base + j);
        }
        s4 = make_int4(sv[0], sv[1], sv[2], sv[3]);
        d4 = make_int4(dv[0], dv[1], dv[2], dv[3]);
        w4 = make_float4(wv[0], wv[1], wv[2], wv[3]);
    }

    int   s[4] = {s4.x, s4.y, s4.z, s4.w};
    int   d[4] = {d4.x, d4.y, d4.z, d4.w};
    float ww[4] = {w4.x, w4.y, w4.z, w4.w};

    float h[4];
#pragma unroll
    for (int j = 0; j < 4; ++j) h[j] = __ldg(g_h2 + s[j]);

#pragma unroll
    for (int j = 0; j < 4; ++j) {
        if (base + j >= E) break;
        atomicAdd(out + d[j], ww[j] * h[j]);
    }
}

// ---------------------------------------------------------------------------
extern "C" void kernel_launch(void* const* d_in, const int* in_sizes, int n_in,
                              void* d_out, int out_size) {
    const float* x   = (const float*)d_in[0];
    const int*   src = (const int*)  d_in[1];
    const int*   dst = (const int*)  d_in[2];
    const float* w   = (const float*)d_in[3];
    const float* W1  = (const float*)d_in[4];
    const float* b1  = (const float*)d_in[5];
    const float* W2  = (const float*)d_in[6];
    const float* b2  = (const float*)d_in[7];
    float* out = (float*)d_out;

    int N = in_sizes[0] / IN_DIM;
    int E = in_sizes[1];

    const int T = 256;

    // slot 1: prep (zero g_h, build B frags, out = b2)
    int n4 = N * HID / 4;
    k_prep<<<(n4 + T - 1) / T, T>>>(W1, b2, out, n4, N);

    // slot 2: tf32 tensor-core gemm
    cudaFuncSetAttribute(k_gemm1,
        cudaFuncAttributeMaxDynamicSharedMemorySize, GSM_B);
    const int GB = 296;
    k_gemm1<<<GB, 384, GSM_B>>>(x, N);

    // slot 3: spmm1 (push-atomic, 2 wf/edge floor)
    int ngroups = (E + 3) >> 2;
    long long t1 = (long long)ngroups * 4;
    k_spmm1<<<(unsigned)((t1 + 511) / 512), 512>>>(src, dst, w, E);

    // slot 4: per-node relu-dot precompute (2 threads/row)
    long long t2 = (long long)N * 2;
    k_layer2a<<<(unsigned)((t2 + 511) / 512), 512>>>(b1, W2, N);

    // slot 5: spmm2 (scalar push-atomic, 4 edges/thread)
    k_spmm2<<<(ngroups + 511) / 512, 512>>>(src, dst, w, out, E);
}